// round 4
// baseline (speedup 1.0000x reference)
#include <cuda_runtime.h>
#include <math.h>

#define NH 4
#define NN 1024
#define EE 4096
#define NLE 16384
#define FN 128
#define FE 64
#define FNO 128
#define FEO 64
#define NODE_OUT_SZ (NH*NN*FNO)   /* 524288 */

// ---------------- scratch (device globals; zero-initialized at load) ----------------
__device__ float g_nv[NN*NH*FN];
__device__ float g_ev[EE*NH*FE];
__device__ float g_nk[NN*NH];          // flat linear output [row][c], c=0..3
__device__ float g_ek[EE*NH];
__device__ float g_yn[NH*4*FN];        // y[h][b][f]  (atomic-accumulated; zeroed each run)
__device__ float g_ye[NH*4*FE];
__device__ float g_un[NH*4*FN];        // u[h][b][j]
__device__ float g_ue[NH*4*FE];
__device__ float g_cn[NH*4];           // c[h][b]
__device__ float g_ce[NH*4];
__device__ float g_nsa[NH*NN];
__device__ float g_esa[NH*EE];
__device__ int   g_cnt_n[NN], g_fc_n[NN], g_off_n[NN+1], g_lst_n[EE];
__device__ int   g_cnt_e[EE], g_fc_e[EE], g_off_e[EE+1], g_lst_e[NLE];
__device__ float g_ncWT[FNO*FN];
__device__ float g_ecWT[FEO*FE];

// ---------------- helpers ----------------
__device__ __forceinline__ float breduce256(float v, float* s)
{
    int lane = threadIdx.x & 31, warp = threadIdx.x >> 5;
#pragma unroll
    for (int o = 16; o; o >>= 1) v += __shfl_xor_sync(0xffffffffu, v, o);
    if (lane == 0) s[warp] = v;
    __syncthreads();
    if (warp == 0) {
        float x = (lane < 8) ? s[lane] : 0.f;
#pragma unroll
        for (int o = 4; o; o >>= 1) x += __shfl_xor_sync(0xffffffffu, x, o);
        if (lane == 0) s[0] = x;
    }
    __syncthreads();
    float r = s[0];
    __syncthreads();
    return r;
}

// ---------------- K1: prep — nk/ek projections, CSR degree counts, weight transposes ----------------
__global__ __launch_bounds__(256)
void prep_kernel(const float* __restrict__ node_in, const float* __restrict__ edge_in,
                 const float* __restrict__ nkW, const float* __restrict__ nkb,
                 const float* __restrict__ ekW, const float* __restrict__ ekb,
                 const int* __restrict__ src, const int* __restrict__ lg_src,
                 const float* __restrict__ ncW, const float* __restrict__ ecW)
{
    int idx = blockIdx.x * blockDim.x + threadIdx.x;
    if (idx < NN*NH) {                                   // nk projection (flat [row][c])
        int row = idx >> 2, c = idx & 3;
        const float* a = node_in + row * FN;
        const float* w = nkW + c * FN;
        float s = nkb[c];
#pragma unroll 4
        for (int k = 0; k < FN; k++) s += a[k] * w[k];
        g_nk[idx] = s;
    } else if (idx < NN*NH + EE*NH) {                    // ek projection
        int j = idx - NN*NH;
        int row = j >> 2, c = j & 3;
        const float* a = edge_in + row * FE;
        const float* w = ekW + c * FE;
        float s = ekb[c];
#pragma unroll 4
        for (int k = 0; k < FE; k++) s += a[k] * w[k];
        g_ek[j] = s;
    } else if (idx < NN*NH + EE*NH + EE) {               // node CSR degree
        int e = idx - (NN*NH + EE*NH);
        atomicAdd(&g_cnt_n[src[e]], 1);
    } else if (idx < NN*NH + EE*NH + EE + NLE) {         // edge CSR degree
        int l = idx - (NN*NH + EE*NH + EE);
        atomicAdd(&g_cnt_e[lg_src[l]], 1);
    } else if (idx < NN*NH + EE*NH + EE + NLE + FNO*FN) { // ncW transpose
        int i = idx - (NN*NH + EE*NH + EE + NLE);
        int o = i >> 7, f = i & 127;
        g_ncWT[f*FNO + o] = ncW[i];
    } else if (idx < NN*NH + EE*NH + EE + NLE + FNO*FN + FEO*FE) { // ecW transpose
        int i = idx - (NN*NH + EE*NH + EE + NLE + FNO*FN);
        int o = i >> 6, f = i & 63;
        g_ecWT[f*FEO + o] = ecW[i];
    }
}

// ---------------- K2: merged tiled SGEMMs (V projections only) ----------------
__device__ __forceinline__
void gemm_tile(const float* __restrict__ A, const float* __restrict__ W,
               const float* __restrict__ bias, float* __restrict__ C,
               int bm, int bn, int Nout, int K)
{
    __shared__ float As[32][64];
    __shared__ float Bs[32][64];
    int tid = threadIdx.x;
    int tx = tid & 15, ty = tid >> 4;

    float acc[4][4];
#pragma unroll
    for (int i = 0; i < 4; i++)
#pragma unroll
        for (int j = 0; j < 4; j++) acc[i][j] = 0.f;

    for (int k0 = 0; k0 < K; k0 += 32) {
#pragma unroll
        for (int j = 0; j < 2; j++) {
            int f4 = tid + j * 256;
            int m  = f4 >> 3;
            int k4 = f4 & 7;
            float4 va = *reinterpret_cast<const float4*>(&A[(size_t)(bm + m) * K + k0 + k4 * 4]);
            As[k4*4+0][m] = va.x; As[k4*4+1][m] = va.y; As[k4*4+2][m] = va.z; As[k4*4+3][m] = va.w;
            float4 vb = *reinterpret_cast<const float4*>(&W[(size_t)(bn + m) * K + k0 + k4 * 4]);
            Bs[k4*4+0][m] = vb.x; Bs[k4*4+1][m] = vb.y; Bs[k4*4+2][m] = vb.z; Bs[k4*4+3][m] = vb.w;
        }
        __syncthreads();
#pragma unroll
        for (int kk = 0; kk < 32; kk++) {
            float4 a = *reinterpret_cast<const float4*>(&As[kk][ty * 4]);
            float4 b = *reinterpret_cast<const float4*>(&Bs[kk][tx * 4]);
            float ra[4] = {a.x, a.y, a.z, a.w};
            float rb[4] = {b.x, b.y, b.z, b.w};
#pragma unroll
            for (int i = 0; i < 4; i++)
#pragma unroll
                for (int j = 0; j < 4; j++) acc[i][j] += ra[i] * rb[j];
        }
        __syncthreads();
    }
#pragma unroll
    for (int i = 0; i < 4; i++) {
        int row = bm + ty * 4 + i;
        int col = bn + tx * 4;
        float4 r;
        r.x = acc[i][0] + bias[col+0];
        r.y = acc[i][1] + bias[col+1];
        r.z = acc[i][2] + bias[col+2];
        r.w = acc[i][3] + bias[col+3];
        *reinterpret_cast<float4*>(&C[(size_t)row * Nout + col]) = r;
    }
}

__global__ __launch_bounds__(256)
void gemms_kernel(const float* __restrict__ nin, const float* __restrict__ ein,
                  const float* __restrict__ nvW, const float* __restrict__ nvb,
                  const float* __restrict__ evW, const float* __restrict__ evb)
{
    int b = blockIdx.x;
    if (b < 128) {
        gemm_tile(nin, nvW, nvb, g_nv, (b >> 3) * 64, (b & 7) * 64, NH*FN, FN);
    } else {
        b -= 128;
        gemm_tile(ein, evW, evb, g_ev, (b >> 2) * 64, (b & 3) * 64, NH*FE, FE);
    }
}

// ---------------- K3: scan of degrees + y[h][b] = X^T k reductions (quadrant-aware) ----------------
__device__ void scan_impl(const int* __restrict__ in, int* __restrict__ out, int items)
{
    __shared__ int sums[1024];
    int tid = threadIdx.x;
    int loc[4];
    int s = 0;
#pragma unroll
    for (int j = 0; j < 4; j++) {
        loc[j] = (j < items) ? in[tid * items + j] : 0;
        s += (j < items) ? loc[j] : 0;
    }
    sums[tid] = s;
    __syncthreads();
    for (int off = 1; off < 1024; off <<= 1) {
        int add = (tid >= off) ? sums[tid - off] : 0;
        __syncthreads();
        sums[tid] += add;
        __syncthreads();
    }
    int run = (tid == 0) ? 0 : sums[tid - 1];
    for (int j = 0; j < items; j++) {
        out[tid * items + j] = run;
        run += loc[j];
    }
    if (tid == 1023) out[1024 * items] = sums[1023];
}

// grid 42 x 1024: bid 0 node scan, bid 1 edge scan, 2..9 node-y (128 rows/blk), 10..41 edge-y
__global__ __launch_bounds__(1024)
void scan_y_kernel(const float* __restrict__ node_in, const float* __restrict__ edge_in)
{
    int bid = blockIdx.x, tid = threadIdx.x;
    if (bid == 0)      scan_impl(g_cnt_n, g_off_n, 1);
    else if (bid == 1) scan_impl(g_cnt_e, g_off_e, 4);
    else if (bid < 10) {
        // node-y: chunk of 128 rows (head h = chunk>>1); f = tid&127, part = tid>>7 (16 rows)
        int chunk = bid - 2;
        int h = chunk >> 1;
        int f = tid & 127, part = tid >> 7;
        int m0 = chunk * 128 + part * 16;
        float acc0 = 0.f, acc1 = 0.f, acc2 = 0.f, acc3 = 0.f;
        for (int m = m0; m < m0 + 16; m++) {
            float x = node_in[m * FN + f];
            const float* kp = g_nk + m * 4;
            acc0 += kp[0] * x; acc1 += kp[1] * x; acc2 += kp[2] * x; acc3 += kp[3] * x;
        }
        atomicAdd(&g_yn[(h*4+0)*FN + f], acc0);
        atomicAdd(&g_yn[(h*4+1)*FN + f], acc1);
        atomicAdd(&g_yn[(h*4+2)*FN + f], acc2);
        atomicAdd(&g_yn[(h*4+3)*FN + f], acc3);
    } else {
        // edge-y: chunk of 128 rows (head h = chunk>>3); f = tid&63, part = tid>>6 (8 rows)
        int chunk = bid - 10;
        int h = chunk >> 3;
        int f = tid & 63, part = tid >> 6;
        int m0 = chunk * 128 + part * 8;
        float acc0 = 0.f, acc1 = 0.f, acc2 = 0.f, acc3 = 0.f;
        for (int m = m0; m < m0 + 8; m++) {
            float x = edge_in[m * FE + f];
            const float* kp = g_ek + m * 4;
            acc0 += kp[0] * x; acc1 += kp[1] * x; acc2 += kp[2] * x; acc3 += kp[3] * x;
        }
        atomicAdd(&g_ye[(h*4+0)*FE + f], acc0);
        atomicAdd(&g_ye[(h*4+1)*FE + f], acc1);
        atomicAdd(&g_ye[(h*4+2)*FE + f], acc2);
        atomicAdd(&g_ye[(h*4+3)*FE + f], acc3);
    }
}

// ---------------- K4: CSR fill + per-head u,c (quadrant-aware) ----------------
// grid 88 x 256: [0,80) fill, 80..83 node heads, 84..87 edge heads
__global__ __launch_bounds__(256)
void fill_uvec_kernel(const int* __restrict__ src, const int* __restrict__ lg_src,
                      const float* __restrict__ nqW, const float* __restrict__ nqb,
                      const float* __restrict__ eqW, const float* __restrict__ eqb)
{
    int bid = blockIdx.x, tid = threadIdx.x;
    if (bid < 80) {
        int idx = bid * 256 + tid;
        if (idx < EE) {
            int s = src[idx];
            int p = g_off_n[s] + atomicAdd(&g_fc_n[s], 1);
            g_lst_n[p] = idx;
        } else if (idx < EE + NLE) {
            int l = idx - EE;
            int s = lg_src[l];
            int p = g_off_e[s] + atomicAdd(&g_fc_e[s], 1);
            g_lst_e[p] = l;
        }
        return;
    }
    __shared__ float tvec[FN];
    __shared__ float ksv[4];
    __shared__ float sred[8];
    int b0 = bid - 80;
    if (b0 < 4) {
        int h = b0;
        // ks[b] = sum_a g_nk[(h*256+a)*4 + b],  a = tid (0..255)
        const float* kp = g_nk + (h*256 + tid) * 4;
        float k0 = kp[0], k1 = kp[1], k2 = kp[2], k3 = kp[3];
        float r0 = breduce256(k0, sred);
        float r1 = breduce256(k1, sred);
        float r2 = breduce256(k2, sred);
        float r3 = breduce256(k3, sred);
        if (tid == 0) { ksv[0] = r0; ksv[1] = r1; ksv[2] = r2; ksv[3] = r3; }
        __syncthreads();
        // t[f] = sum_b ( bq[b*128+f]*ks[b] + sum_j Wq[b*128+f, j] * y[h][b][j] )
        if (tid < FN) {
            int f = tid;
            float acc = 0.f;
#pragma unroll
            for (int b = 0; b < 4; b++) {
                const float* wrow = nqW + (size_t)(b*FN + f) * FN;
                const float* yb = g_yn + (h*4 + b) * FN;
                float a = nqb[b*FN + f] * ksv[b];
#pragma unroll 4
                for (int j = 0; j < FN; j++) a += wrow[j] * yb[j];
                acc += a;
            }
            tvec[f] = acc;
        }
        __syncthreads();
        // u[b][j] = sum_f Wq[b*128+f, j] * t[f]   (512 outputs, 2 per thread)
#pragma unroll
        for (int rep = 0; rep < 2; rep++) {
            int o = rep * 256 + tid;
            int b = o >> 7, j = o & 127;
            float acc = 0.f;
#pragma unroll 4
            for (int f = 0; f < FN; f++) acc += nqW[(size_t)(b*FN + f) * FN + j] * tvec[f];
            g_un[(h*4 + b)*FN + j] = acc;
        }
        // c[b] = sum_f bq[b*128+f] * t[f]
#pragma unroll
        for (int b = 0; b < 4; b++) {
            float pc = (tid < FN) ? nqb[b*FN + tid] * tvec[tid] : 0.f;
            float c = breduce256(pc, sred);
            if (tid == 0) g_cn[h*4 + b] = c;
        }
    } else {
        int h = b0 - 4;
        // ks[b] = sum_a g_ek[(h*1024+a)*4 + b]
        float k0 = 0.f, k1 = 0.f, k2 = 0.f, k3 = 0.f;
        for (int a = tid; a < 1024; a += 256) {
            const float* kp = g_ek + (h*1024 + a) * 4;
            k0 += kp[0]; k1 += kp[1]; k2 += kp[2]; k3 += kp[3];
        }
        float r0 = breduce256(k0, sred);
        float r1 = breduce256(k1, sred);
        float r2 = breduce256(k2, sred);
        float r3 = breduce256(k3, sred);
        if (tid == 0) { ksv[0] = r0; ksv[1] = r1; ksv[2] = r2; ksv[3] = r3; }
        __syncthreads();
        if (tid < FE) {
            int f = tid;
            float acc = 0.f;
#pragma unroll
            for (int b = 0; b < 4; b++) {
                const float* wrow = eqW + (size_t)(b*FE + f) * FE;
                const float* yb = g_ye + (h*4 + b) * FE;
                float a = eqb[b*FE + f] * ksv[b];
#pragma unroll 4
                for (int j = 0; j < FE; j++) a += wrow[j] * yb[j];
                acc += a;
            }
            tvec[f] = acc;
        }
        __syncthreads();
        // u[b][j]: 256 outputs, one per thread
        {
            int b = tid >> 6, j = tid & 63;
            float acc = 0.f;
#pragma unroll 4
            for (int f = 0; f < FE; f++) acc += eqW[(size_t)(b*FE + f) * FE + j] * tvec[f];
            g_ue[(h*4 + b)*FE + j] = acc;
        }
#pragma unroll
        for (int b = 0; b < 4; b++) {
            float pc = (tid < FE) ? eqb[b*FE + tid] * tvec[tid] : 0.f;
            float c = breduce256(pc, sred);
            if (tid == 0) g_ce[h*4 + b] = c;
        }
    }
}

// ---------------- K5: raw scores s[h, 4a+b] = X[row].u[h][b] + c[h][b] ----------------
__global__ __launch_bounds__(256)
void scores_kernel(const float* __restrict__ node_in, const float* __restrict__ edge_in)
{
    int w = blockIdx.x * 8 + (threadIdx.x >> 5);
    int lane = threadIdx.x & 31;
    if (w < NH*NN) {
        int h = w >> 10, m = w & (NN - 1);
        int a = m >> 2, b = m & 3;
        int row = h * 256 + a;
        float4 uv = *reinterpret_cast<const float4*>(&g_un[(h*4+b)*FN + lane*4]);
        float4 xv = *reinterpret_cast<const float4*>(&node_in[row*FN + lane*4]);
        float d = xv.x*uv.x + xv.y*uv.y + xv.z*uv.z + xv.w*uv.w;
#pragma unroll
        for (int o = 16; o; o >>= 1) d += __shfl_xor_sync(0xffffffffu, d, o);
        if (lane == 0) g_nsa[h*NN + m] = d + g_cn[h*4+b];
    } else {
        int w2 = w - NH*NN;
        int h = w2 >> 12, m = w2 & (EE - 1);
        int a = m >> 2, b = m & 3;
        int row = h * 1024 + a;
        float2 uv = *reinterpret_cast<const float2*>(&g_ue[(h*4+b)*FE + lane*2]);
        float2 xv = *reinterpret_cast<const float2*>(&edge_in[row*FE + lane*2]);
        float d = xv.x*uv.x + xv.y*uv.y;
#pragma unroll
        for (int o = 16; o; o >>= 1) d += __shfl_xor_sync(0xffffffffu, d, o);
        if (lane == 0) g_esa[h*EE + m] = d + g_ce[h*4+b];
    }
}

// ---------------- K6: per-head softmax normalize (in place) ----------------
__global__ __launch_bounds__(1024)
void softmax_kernel()
{
    __shared__ float red[32];
    __shared__ float bc_max, bc_sum;
    int bid = blockIdx.x, tid = threadIdx.x;
    int warp = tid >> 5, lane = tid & 31;
    float* buf; int cnt;
    if (bid < 4) { buf = g_nsa + bid * NN;       cnt = 1; }
    else         { buf = g_esa + (bid - 4) * EE; cnt = 4; }

    float v[4];
    float m = -1e30f;
    for (int j = 0; j < cnt; j++) { v[j] = buf[tid + j*1024]; m = fmaxf(m, v[j]); }
#pragma unroll
    for (int o = 16; o; o >>= 1) m = fmaxf(m, __shfl_xor_sync(0xffffffffu, m, o));
    if (lane == 0) red[warp] = m;
    __syncthreads();
    if (tid == 0) {
        float x = red[0];
        for (int w = 1; w < 32; w++) x = fmaxf(x, red[w]);
        bc_max = x;
    }
    __syncthreads();
    float mx = bc_max;

    float sum = 0.f;
    for (int j = 0; j < cnt; j++) { v[j] = expf(v[j] - mx); sum += v[j]; }
#pragma unroll
    for (int o = 16; o; o >>= 1) sum += __shfl_xor_sync(0xffffffffu, sum, o);
    __syncthreads();
    if (lane == 0) red[warp] = sum;
    __syncthreads();
    if (tid == 0) {
        float x = 0.f;
        for (int w = 0; w < 32; w++) x += red[w];
        bc_sum = x;
    }
    __syncthreads();
    float inv = 1.f / bc_sum;
    for (int j = 0; j < cnt; j++) buf[tid + j*1024] = v[j] * inv;
}

// ---------------- K7: merged outputs + cleanup ----------------
// grid 2064 x 128: [0,1024) node (4 rows/blk), [1024,2048) edge (16 rows/blk), [2048,2064) cleanup
__global__ __launch_bounds__(128)
void out_kernel(const int* __restrict__ dst, const int* __restrict__ lg_dst,
                const float* __restrict__ ncb, const float* __restrict__ ecb,
                float* __restrict__ out)
{
    int bid = blockIdx.x, tid = threadIdx.x;
    if (bid < 1024) {
        __shared__ float agg[4][FN];
        int h = bid >> 8;
        int i0 = (bid & 255) * 4;
#pragma unroll
        for (int r = 0; r < 4; r++) {
            int i = i0 + r;
            int s0 = g_off_n[i], s1 = g_off_n[i + 1];
            float acc = 0.f;
            for (int p = s0; p < s1; p++) {
                int e = g_lst_n[p];
                int d = dst[e];
                bool win = true;
                for (int p2 = s0; p2 < s1; p2++) {
                    int e2 = g_lst_n[p2];
                    if (e2 > e && dst[e2] == d) win = false;   // last write wins
                }
                if (win) acc += g_esa[h*EE + e] * g_nv[h*(NN*FN) + d*FN + tid];
            }
            agg[r][tid] = acc;
        }
        __syncthreads();
        float b = ncb[tid];
        float a0 = b, a1 = b, a2 = b, a3 = b;
#pragma unroll 4
        for (int f = 0; f < FN; f++) {
            float w = g_ncWT[f*FNO + tid];
            a0 += agg[0][f] * w;
            a1 += agg[1][f] * w;
            a2 += agg[2][f] * w;
            a3 += agg[3][f] * w;
        }
        float* o = out + h*(NN*FNO) + i0*FNO + tid;
        o[0*FNO] = fmaxf(a0, 0.f);
        o[1*FNO] = fmaxf(a1, 0.f);
        o[2*FNO] = fmaxf(a2, 0.f);
        o[3*FNO] = fmaxf(a3, 0.f);
    } else if (bid < 2048) {
        __shared__ float agg[16][FEO];
        int b = bid - 1024;
        int h = b >> 8;
        int i0 = (b & 255) * 16;
        int col = tid & 63, rg = tid >> 6;
#pragma unroll
        for (int k = 0; k < 8; k++) {
            int lr = rg * 8 + k;
            int i = i0 + lr;
            int s0 = g_off_e[i], s1 = g_off_e[i + 1];
            float acc = 0.f;
            for (int p = s0; p < s1; p++) {
                int l = g_lst_e[p];
                int ld = lg_dst[l];
                bool win = true;
                for (int p2 = s0; p2 < s1; p2++) {
                    int l2 = g_lst_e[p2];
                    if (l2 > l && lg_dst[l2] == ld) win = false;
                }
                if (win) acc += g_ev[h*(EE*FE) + ld*FE + col];
            }
            acc *= g_nsa[h*NN + dst[i]];
            agg[lr][col] = acc;
        }
        __syncthreads();
        float a[8];
        float bb = ecb[col];
#pragma unroll
        for (int k = 0; k < 8; k++) a[k] = bb;
#pragma unroll 4
        for (int f = 0; f < FE; f++) {
            float w = g_ecWT[f*FEO + col];
#pragma unroll
            for (int k = 0; k < 8; k++) a[k] += agg[rg*8 + k][f] * w;
        }
#pragma unroll
        for (int k = 0; k < 8; k++) {
            int i = i0 + rg*8 + k;
            out[NODE_OUT_SZ + h*(EE*FEO) + i*FEO + col] = fmaxf(a[k], 0.f);
        }
    } else {
        // cleanup for next run
        int idx = (bid - 2048) * 128 + tid;       // 0..2047
        for (int i = idx; i < NN; i += 2048) { g_cnt_n[i] = 0; g_fc_n[i] = 0; }
        for (int i = idx; i < EE; i += 2048) { g_cnt_e[i] = 0; g_fc_e[i] = 0; }
        for (int i = idx; i < NH*4*FN; i += 2048) g_yn[i] = 0.f;
        for (int i = idx; i < NH*4*FE; i += 2048) g_ye[i] = 0.f;
    }
}

// ---------------- launcher ----------------
extern "C" void kernel_launch(void* const* d_in, const int* in_sizes, int n_in,
                              void* d_out, int out_size)
{
    const float* node_inputs = (const float*)d_in[0];
    const float* edge_inputs = (const float*)d_in[1];
    const int*   src         = (const int*)d_in[2];
    const int*   dst         = (const int*)d_in[3];
    const int*   lg_src      = (const int*)d_in[4];
    const int*   lg_dst      = (const int*)d_in[5];
    const float* nqW = (const float*)d_in[6];
    const float* nqb = (const float*)d_in[7];
    const float* nkW = (const float*)d_in[8];
    const float* nkb = (const float*)d_in[9];
    const float* nvW = (const float*)d_in[10];
    const float* nvb = (const float*)d_in[11];
    const float* eqW = (const float*)d_in[12];
    const float* eqb = (const float*)d_in[13];
    const float* ekW = (const float*)d_in[14];
    const float* ekb = (const float*)d_in[15];
    const float* evW = (const float*)d_in[16];
    const float* evb = (const float*)d_in[17];
    const float* ncW = (const float*)d_in[18];
    const float* ncb = (const float*)d_in[19];
    const float* ecW = (const float*)d_in[20];
    const float* ecb = (const float*)d_in[21];
    float* out = (float*)d_out;

    prep_kernel<<<240, 256>>>(node_inputs, edge_inputs, nkW, nkb, ekW, ekb,
                              src, lg_src, ncW, ecW);
    gemms_kernel<<<384, 256>>>(node_inputs, edge_inputs, nvW, nvb, evW, evb);
    scan_y_kernel<<<42, 1024>>>(node_inputs, edge_inputs);
    fill_uvec_kernel<<<88, 256>>>(src, lg_src, nqW, nqb, eqW, eqb);
    scores_kernel<<<2560, 256>>>(node_inputs, edge_inputs);
    softmax_kernel<<<8, 1024>>>();
    out_kernel<<<2064, 128>>>(dst, lg_dst, ncb, ecb, out);
}

// round 5
// speedup vs baseline: 1.5702x; 1.5702x over previous
#include <cuda_runtime.h>
#include <math.h>

#define NH 4
#define NN 1024
#define EE 4096
#define NLE 16384
#define FN 128
#define FE 64
#define FNO 128
#define FEO 64
#define NODE_OUT_SZ (NH*NN*FNO)   /* 524288 */

// ---------------- scratch (device globals; zero-initialized at load) ----------------
__device__ float g_nv[NN*NH*FN];
__device__ float g_ev[EE*NH*FE];
__device__ float g_nk[NN*NH];          // flat linear output [row][c]
__device__ float g_ek[EE*NH];
__device__ float g_yn[NH*4*FN];        // y[h][b][f]   (atomics; zeroed each run)
__device__ float g_ye[NH*4*FE];
__device__ float g_ksn[NH*4];          // ks[h][b]     (atomics; zeroed each run)
__device__ float g_kse[NH*4];
__device__ float g_tn2[NH*FN];         // t[h][f]
__device__ float g_te2[NH*FE];
__device__ float g_un[NH*4*FN];        // u[h][b][j]
__device__ float g_ue[NH*4*FE];
__device__ float g_cn[NH*4];           // c[h][b]
__device__ float g_ce[NH*4];
__device__ float g_nsa[NH*NN];
__device__ float g_esa[NH*EE];
__device__ int   g_cnt_n[NN], g_fc_n[NN], g_off_n[NN+1], g_lst_n[EE];
__device__ int   g_cnt_e[EE], g_fc_e[EE], g_off_e[EE+1], g_lst_e[NLE];
__device__ float g_ncWT[FNO*FN];
__device__ float g_ecWT[FEO*FE];
__device__ float g_nqWT[FN*(4*FN)];    // nqWT[j*512 + o] = nqW[o*128 + j]
__device__ float g_eqWT[FE*(4*FE)];    // eqWT[j*256 + o] = eqW[o*64 + j]

__device__ __forceinline__ float wredsum(float v)
{
#pragma unroll
    for (int o = 16; o; o >>= 1) v += __shfl_xor_sync(0xffffffffu, v, o);
    return v;
}

// ---------------- K1: prep — warp k-projections, CSR counts, weight transposes ----------------
// grid 1120 x 256: [0,640) projections, [640,720) counts, [720,1120) transposes
__global__ __launch_bounds__(256)
void prep_kernel(const float* __restrict__ node_in, const float* __restrict__ edge_in,
                 const float* __restrict__ nkW, const float* __restrict__ nkb,
                 const float* __restrict__ ekW, const float* __restrict__ ekb,
                 const int* __restrict__ src, const int* __restrict__ lg_src,
                 const float* __restrict__ ncW, const float* __restrict__ ecW,
                 const float* __restrict__ nqW, const float* __restrict__ eqW)
{
    int bid = blockIdx.x, tid = threadIdx.x;
    if (bid < 640) {
        int w = bid * 8 + (tid >> 5), lane = tid & 31;
        if (w < NN) {
            float4 xv = reinterpret_cast<const float4*>(node_in + w * FN)[lane];
            float4 w0 = reinterpret_cast<const float4*>(nkW + 0*FN)[lane];
            float4 w1 = reinterpret_cast<const float4*>(nkW + 1*FN)[lane];
            float4 w2 = reinterpret_cast<const float4*>(nkW + 2*FN)[lane];
            float4 w3 = reinterpret_cast<const float4*>(nkW + 3*FN)[lane];
            float p0 = xv.x*w0.x + xv.y*w0.y + xv.z*w0.z + xv.w*w0.w;
            float p1 = xv.x*w1.x + xv.y*w1.y + xv.z*w1.z + xv.w*w1.w;
            float p2 = xv.x*w2.x + xv.y*w2.y + xv.z*w2.z + xv.w*w2.w;
            float p3 = xv.x*w3.x + xv.y*w3.y + xv.z*w3.z + xv.w*w3.w;
            p0 = wredsum(p0); p1 = wredsum(p1); p2 = wredsum(p2); p3 = wredsum(p3);
            if (lane < 4) {
                float v = (lane == 0) ? p0 : (lane == 1) ? p1 : (lane == 2) ? p2 : p3;
                g_nk[w * 4 + lane] = v + nkb[lane];
            }
        } else {
            int row = w - NN;     // 0..4095
            float2 xv = reinterpret_cast<const float2*>(edge_in + row * FE)[lane];
            float2 w0 = reinterpret_cast<const float2*>(ekW + 0*FE)[lane];
            float2 w1 = reinterpret_cast<const float2*>(ekW + 1*FE)[lane];
            float2 w2 = reinterpret_cast<const float2*>(ekW + 2*FE)[lane];
            float2 w3 = reinterpret_cast<const float2*>(ekW + 3*FE)[lane];
            float p0 = xv.x*w0.x + xv.y*w0.y;
            float p1 = xv.x*w1.x + xv.y*w1.y;
            float p2 = xv.x*w2.x + xv.y*w2.y;
            float p3 = xv.x*w3.x + xv.y*w3.y;
            p0 = wredsum(p0); p1 = wredsum(p1); p2 = wredsum(p2); p3 = wredsum(p3);
            if (lane < 4) {
                float v = (lane == 0) ? p0 : (lane == 1) ? p1 : (lane == 2) ? p2 : p3;
                g_ek[row * 4 + lane] = v + ekb[lane];
            }
        }
    } else if (bid < 720) {
        int idx = (bid - 640) * 256 + tid;
        if (idx < EE)            atomicAdd(&g_cnt_n[src[idx]], 1);
        else if (idx < EE + NLE) atomicAdd(&g_cnt_e[lg_src[idx - EE]], 1);
    } else {
        int idx = (bid - 720) * 256 + tid;     // 0..102399
        if (idx < FNO*FN) {
            int o = idx >> 7, f = idx & 127;
            g_ncWT[f*FNO + o] = ncW[idx];
        } else if (idx < FNO*FN + FEO*FE) {
            int i = idx - FNO*FN;
            int o = i >> 6, f = i & 63;
            g_ecWT[f*FEO + o] = ecW[i];
        } else if (idx < FNO*FN + FEO*FE + 512*FN) {
            int i = idx - (FNO*FN + FEO*FE);
            int o = i >> 7, j = i & 127;
            g_nqWT[j*512 + o] = nqW[i];
        } else {
            int i = idx - (FNO*FN + FEO*FE + 512*FN);
            int o = i >> 6, j = i & 63;
            g_eqWT[j*256 + o] = eqW[i];
        }
    }
}

// ---------------- K2: merged tiled SGEMMs (V projections) ----------------
__device__ __forceinline__
void gemm_tile(const float* __restrict__ A, const float* __restrict__ W,
               const float* __restrict__ bias, float* __restrict__ C,
               int bm, int bn, int Nout, int K)
{
    __shared__ float As[32][64];
    __shared__ float Bs[32][64];
    int tid = threadIdx.x;
    int tx = tid & 15, ty = tid >> 4;

    float acc[4][4];
#pragma unroll
    for (int i = 0; i < 4; i++)
#pragma unroll
        for (int j = 0; j < 4; j++) acc[i][j] = 0.f;

    for (int k0 = 0; k0 < K; k0 += 32) {
#pragma unroll
        for (int j = 0; j < 2; j++) {
            int f4 = tid + j * 256;
            int m  = f4 >> 3;
            int k4 = f4 & 7;
            float4 va = *reinterpret_cast<const float4*>(&A[(size_t)(bm + m) * K + k0 + k4 * 4]);
            As[k4*4+0][m] = va.x; As[k4*4+1][m] = va.y; As[k4*4+2][m] = va.z; As[k4*4+3][m] = va.w;
            float4 vb = *reinterpret_cast<const float4*>(&W[(size_t)(bn + m) * K + k0 + k4 * 4]);
            Bs[k4*4+0][m] = vb.x; Bs[k4*4+1][m] = vb.y; Bs[k4*4+2][m] = vb.z; Bs[k4*4+3][m] = vb.w;
        }
        __syncthreads();
#pragma unroll
        for (int kk = 0; kk < 32; kk++) {
            float4 a = *reinterpret_cast<const float4*>(&As[kk][ty * 4]);
            float4 b = *reinterpret_cast<const float4*>(&Bs[kk][tx * 4]);
            float ra[4] = {a.x, a.y, a.z, a.w};
            float rb[4] = {b.x, b.y, b.z, b.w};
#pragma unroll
            for (int i = 0; i < 4; i++)
#pragma unroll
                for (int j = 0; j < 4; j++) acc[i][j] += ra[i] * rb[j];
        }
        __syncthreads();
    }
#pragma unroll
    for (int i = 0; i < 4; i++) {
        int row = bm + ty * 4 + i;
        int col = bn + tx * 4;
        float4 r;
        r.x = acc[i][0] + bias[col+0];
        r.y = acc[i][1] + bias[col+1];
        r.z = acc[i][2] + bias[col+2];
        r.w = acc[i][3] + bias[col+3];
        *reinterpret_cast<float4*>(&C[(size_t)row * Nout + col]) = r;
    }
}

__global__ __launch_bounds__(256)
void gemms_kernel(const float* __restrict__ nin, const float* __restrict__ ein,
                  const float* __restrict__ nvW, const float* __restrict__ nvb,
                  const float* __restrict__ evW, const float* __restrict__ evb)
{
    int b = blockIdx.x;
    if (b < 128) {
        gemm_tile(nin, nvW, nvb, g_nv, (b >> 3) * 64, (b & 7) * 64, NH*FN, FN);
    } else {
        b -= 128;
        gemm_tile(ein, evW, evb, g_ev, (b >> 2) * 64, (b & 3) * 64, NH*FE, FE);
    }
}

// ---------------- K3: scan of degrees + y[h][b] + ks[h][b] reductions ----------------
__device__ void scan_impl(const int* __restrict__ in, int* __restrict__ out, int items)
{
    __shared__ int sums[1024];
    int tid = threadIdx.x;
    int loc[4];
    int s = 0;
#pragma unroll
    for (int j = 0; j < 4; j++) {
        loc[j] = (j < items) ? in[tid * items + j] : 0;
        s += (j < items) ? loc[j] : 0;
    }
    sums[tid] = s;
    __syncthreads();
    for (int off = 1; off < 1024; off <<= 1) {
        int add = (tid >= off) ? sums[tid - off] : 0;
        __syncthreads();
        sums[tid] += add;
        __syncthreads();
    }
    int run = (tid == 0) ? 0 : sums[tid - 1];
    for (int j = 0; j < items; j++) {
        out[tid * items + j] = run;
        run += loc[j];
    }
    if (tid == 1023) out[1024 * items] = sums[1023];
}

// grid 42 x 1024: bid 0 node scan, bid 1 edge scan, 2..9 node-y, 10..41 edge-y
__global__ __launch_bounds__(1024)
void scan_y_kernel(const float* __restrict__ node_in, const float* __restrict__ edge_in)
{
    int bid = blockIdx.x, tid = threadIdx.x;
    if (bid == 0)      scan_impl(g_cnt_n, g_off_n, 1);
    else if (bid == 1) scan_impl(g_cnt_e, g_off_e, 4);
    else if (bid < 10) {
        int chunk = bid - 2;
        int h = chunk >> 1;
        int f = tid & 127, part = tid >> 7;
        int m0 = chunk * 128 + part * 16;
        float acc0 = 0.f, acc1 = 0.f, acc2 = 0.f, acc3 = 0.f;
        for (int m = m0; m < m0 + 16; m++) {
            float x = node_in[m * FN + f];
            const float* kp = g_nk + m * 4;
            acc0 += kp[0] * x; acc1 += kp[1] * x; acc2 += kp[2] * x; acc3 += kp[3] * x;
        }
        atomicAdd(&g_yn[(h*4+0)*FN + f], acc0);
        atomicAdd(&g_yn[(h*4+1)*FN + f], acc1);
        atomicAdd(&g_yn[(h*4+2)*FN + f], acc2);
        atomicAdd(&g_yn[(h*4+3)*FN + f], acc3);
        if (f < 4) {                     // ks partial over these 16 rows
            float s = 0.f;
            for (int m = m0; m < m0 + 16; m++) s += g_nk[m * 4 + f];
            atomicAdd(&g_ksn[h*4 + f], s);
        }
    } else {
        int chunk = bid - 10;
        int h = chunk >> 3;
        int f = tid & 63, part = tid >> 6;
        int m0 = chunk * 128 + part * 8;
        float acc0 = 0.f, acc1 = 0.f, acc2 = 0.f, acc3 = 0.f;
        for (int m = m0; m < m0 + 8; m++) {
            float x = edge_in[m * FE + f];
            const float* kp = g_ek + m * 4;
            acc0 += kp[0] * x; acc1 += kp[1] * x; acc2 += kp[2] * x; acc3 += kp[3] * x;
        }
        atomicAdd(&g_ye[(h*4+0)*FE + f], acc0);
        atomicAdd(&g_ye[(h*4+1)*FE + f], acc1);
        atomicAdd(&g_ye[(h*4+2)*FE + f], acc2);
        atomicAdd(&g_ye[(h*4+3)*FE + f], acc3);
        if (f < 4) {
            float s = 0.f;
            for (int m = m0; m < m0 + 8; m++) s += g_ek[m * 4 + f];
            atomicAdd(&g_kse[h*4 + f], s);
        }
    }
}

// ---------------- K4: CSR fill + t computation (warp per (h,f)) ----------------
// grid 176 x 256: [0,80) fill, [80,176) t warps (768 total: 512 node + 256 edge)
__global__ __launch_bounds__(256)
void fill_t_kernel(const int* __restrict__ src, const int* __restrict__ lg_src,
                   const float* __restrict__ nqW, const float* __restrict__ nqb,
                   const float* __restrict__ eqW, const float* __restrict__ eqb)
{
    int bid = blockIdx.x, tid = threadIdx.x;
    if (bid < 80) {
        int idx = bid * 256 + tid;
        if (idx < EE) {
            int s = src[idx];
            int p = g_off_n[s] + atomicAdd(&g_fc_n[s], 1);
            g_lst_n[p] = idx;
        } else if (idx < EE + NLE) {
            int l = idx - EE;
            int s = lg_src[l];
            int p = g_off_e[s] + atomicAdd(&g_fc_e[s], 1);
            g_lst_e[p] = l;
        }
        return;
    }
    int w = (bid - 80) * 8 + (tid >> 5), lane = tid & 31;
    if (w < 512) {
        // node t[h][f] = sum_b ( nqb[b*128+f]*ks[h,b] + sum_j nqW[(b*128+f)*128+j]*y[h,b,j] )
        int h = w >> 7, f = w & 127;
        float acc = 0.f;
#pragma unroll
        for (int b = 0; b < 4; b++) {
            float4 wv = *reinterpret_cast<const float4*>(&nqW[(size_t)(b*FN + f) * FN + lane*4]);
            float4 yv = *reinterpret_cast<const float4*>(&g_yn[(h*4 + b)*FN + lane*4]);
            acc += wv.x*yv.x + wv.y*yv.y + wv.z*yv.z + wv.w*yv.w;
        }
        acc = wredsum(acc);
        if (lane == 0) {
            float bias_term = 0.f;
#pragma unroll
            for (int b = 0; b < 4; b++) bias_term += nqb[b*FN + f] * g_ksn[h*4 + b];
            g_tn2[h*FN + f] = acc + bias_term;
        }
    } else if (w < 768) {
        int w2 = w - 512;
        int h = w2 >> 6, f = w2 & 63;
        float acc = 0.f;
#pragma unroll
        for (int b = 0; b < 4; b++) {
            float2 wv = *reinterpret_cast<const float2*>(&eqW[(size_t)(b*FE + f) * FE + lane*2]);
            float2 yv = *reinterpret_cast<const float2*>(&g_ye[(h*4 + b)*FE + lane*2]);
            acc += wv.x*yv.x + wv.y*yv.y;
        }
        acc = wredsum(acc);
        if (lane == 0) {
            float bias_term = 0.f;
#pragma unroll
            for (int b = 0; b < 4; b++) bias_term += eqb[b*FE + f] * g_kse[h*4 + b];
            g_te2[h*FE + f] = acc + bias_term;
        }
    }
}

// ---------------- K5: u[h][b][j] + c[h][b] (warp per output) ----------------
// grid 388 x 256: warps [0,2048) node u, [2048,3072) edge u, [3072,3088) node c, [3088,3104) edge c
__global__ __launch_bounds__(256)
void uc_kernel(const float* __restrict__ nqb, const float* __restrict__ eqb)
{
    int w = blockIdx.x * 8 + (threadIdx.x >> 5), lane = threadIdx.x & 31;
    if (w < 2048) {
        int h = w >> 9, b = (w >> 7) & 3, j = w & 127;
        float4 wv = *reinterpret_cast<const float4*>(&g_nqWT[j*512 + b*FN + lane*4]);
        float4 tv = *reinterpret_cast<const float4*>(&g_tn2[h*FN + lane*4]);
        float acc = wv.x*tv.x + wv.y*tv.y + wv.z*tv.z + wv.w*tv.w;
        acc = wredsum(acc);
        if (lane == 0) g_un[(h*4 + b)*FN + j] = acc;
    } else if (w < 3072) {
        int w2 = w - 2048;
        int h = w2 >> 8, b = (w2 >> 6) & 3, j = w2 & 63;
        float2 wv = *reinterpret_cast<const float2*>(&g_eqWT[j*256 + b*FE + lane*2]);
        float2 tv = *reinterpret_cast<const float2*>(&g_te2[h*FE + lane*2]);
        float acc = wv.x*tv.x + wv.y*tv.y;
        acc = wredsum(acc);
        if (lane == 0) g_ue[(h*4 + b)*FE + j] = acc;
    } else if (w < 3088) {
        int w3 = w - 3072;
        int h = w3 >> 2, b = w3 & 3;
        float4 bv = *reinterpret_cast<const float4*>(&nqb[b*FN + lane*4]);
        float4 tv = *reinterpret_cast<const float4*>(&g_tn2[h*FN + lane*4]);
        float acc = bv.x*tv.x + bv.y*tv.y + bv.z*tv.z + bv.w*tv.w;
        acc = wredsum(acc);
        if (lane == 0) g_cn[h*4 + b] = acc;
    } else if (w < 3104) {
        int w3 = w - 3088;
        int h = w3 >> 2, b = w3 & 3;
        float2 bv = *reinterpret_cast<const float2*>(&eqb[b*FE + lane*2]);
        float2 tv = *reinterpret_cast<const float2*>(&g_te2[h*FE + lane*2]);
        float acc = bv.x*tv.x + bv.y*tv.y;
        acc = wredsum(acc);
        if (lane == 0) g_ce[h*4 + b] = acc;
    }
}

// ---------------- K6: raw scores s[h, 4a+b] = X[row].u[h][b] + c[h][b] ----------------
__global__ __launch_bounds__(256)
void scores_kernel(const float* __restrict__ node_in, const float* __restrict__ edge_in)
{
    int w = blockIdx.x * 8 + (threadIdx.x >> 5);
    int lane = threadIdx.x & 31;
    if (w < NH*NN) {
        int h = w >> 10, m = w & (NN - 1);
        int a = m >> 2, b = m & 3;
        int row = h * 256 + a;
        float4 uv = *reinterpret_cast<const float4*>(&g_un[(h*4+b)*FN + lane*4]);
        float4 xv = *reinterpret_cast<const float4*>(&node_in[row*FN + lane*4]);
        float d = xv.x*uv.x + xv.y*uv.y + xv.z*uv.z + xv.w*uv.w;
        d = wredsum(d);
        if (lane == 0) g_nsa[h*NN + m] = d + g_cn[h*4+b];
    } else {
        int w2 = w - NH*NN;
        int h = w2 >> 12, m = w2 & (EE - 1);
        int a = m >> 2, b = m & 3;
        int row = h * 1024 + a;
        float2 uv = *reinterpret_cast<const float2*>(&g_ue[(h*4+b)*FE + lane*2]);
        float2 xv = *reinterpret_cast<const float2*>(&edge_in[row*FE + lane*2]);
        float d = xv.x*uv.x + xv.y*uv.y;
        d = wredsum(d);
        if (lane == 0) g_esa[h*EE + m] = d + g_ce[h*4+b];
    }
}

// ---------------- K7: per-head softmax normalize (in place) ----------------
__global__ __launch_bounds__(1024)
void softmax_kernel()
{
    __shared__ float red[32];
    __shared__ float bc_max, bc_sum;
    int bid = blockIdx.x, tid = threadIdx.x;
    int warp = tid >> 5, lane = tid & 31;
    float* buf; int cnt;
    if (bid < 4) { buf = g_nsa + bid * NN;       cnt = 1; }
    else         { buf = g_esa + (bid - 4) * EE; cnt = 4; }

    float v[4];
    float m = -1e30f;
    for (int j = 0; j < cnt; j++) { v[j] = buf[tid + j*1024]; m = fmaxf(m, v[j]); }
#pragma unroll
    for (int o = 16; o; o >>= 1) m = fmaxf(m, __shfl_xor_sync(0xffffffffu, m, o));
    if (lane == 0) red[warp] = m;
    __syncthreads();
    if (tid == 0) {
        float x = red[0];
        for (int w = 1; w < 32; w++) x = fmaxf(x, red[w]);
        bc_max = x;
    }
    __syncthreads();
    float mx = bc_max;

    float sum = 0.f;
    for (int j = 0; j < cnt; j++) { v[j] = expf(v[j] - mx); sum += v[j]; }
#pragma unroll
    for (int o = 16; o; o >>= 1) sum += __shfl_xor_sync(0xffffffffu, sum, o);
    __syncthreads();
    if (lane == 0) red[warp] = sum;
    __syncthreads();
    if (tid == 0) {
        float x = 0.f;
        for (int w = 0; w < 32; w++) x += red[w];
        bc_sum = x;
    }
    __syncthreads();
    float inv = 1.f / bc_sum;
    for (int j = 0; j < cnt; j++) buf[tid + j*1024] = v[j] * inv;
}

// ---------------- K8: merged outputs + cleanup ----------------
// grid 2064 x 128: [0,1024) node (4 rows/blk), [1024,2048) edge (16 rows/blk), [2048,2064) cleanup
__global__ __launch_bounds__(128)
void out_kernel(const int* __restrict__ dst, const int* __restrict__ lg_dst,
                const float* __restrict__ ncb, const float* __restrict__ ecb,
                float* __restrict__ out)
{
    int bid = blockIdx.x, tid = threadIdx.x;
    if (bid < 1024) {
        __shared__ float agg[4][FN];
        int h = bid >> 8;
        int i0 = (bid & 255) * 4;
#pragma unroll
        for (int r = 0; r < 4; r++) {
            int i = i0 + r;
            int s0 = g_off_n[i], s1 = g_off_n[i + 1];
            float acc = 0.f;
            for (int p = s0; p < s1; p++) {
                int e = g_lst_n[p];
                int d = dst[e];
                bool win = true;
                for (int p2 = s0; p2 < s1; p2++) {
                    int e2 = g_lst_n[p2];
                    if (e2 > e && dst[e2] == d) win = false;   // last write wins
                }
                if (win) acc += g_esa[h*EE + e] * g_nv[h*(NN*FN) + d*FN + tid];
            }
            agg[r][tid] = acc;
        }
        __syncthreads();
        float b = ncb[tid];
        float a0 = b, a1 = b, a2 = b, a3 = b;
#pragma unroll 4
        for (int f = 0; f < FN; f++) {
            float w = g_ncWT[f*FNO + tid];
            a0 += agg[0][f] * w;
            a1 += agg[1][f] * w;
            a2 += agg[2][f] * w;
            a3 += agg[3][f] * w;
        }
        float* o = out + h*(NN*FNO) + i0*FNO + tid;
        o[0*FNO] = fmaxf(a0, 0.f);
        o[1*FNO] = fmaxf(a1, 0.f);
        o[2*FNO] = fmaxf(a2, 0.f);
        o[3*FNO] = fmaxf(a3, 0.f);
    } else if (bid < 2048) {
        __shared__ float agg[16][FEO];
        int b = bid - 1024;
        int h = b >> 8;
        int i0 = (b & 255) * 16;
        int col = tid & 63, rg = tid >> 6;
#pragma unroll
        for (int k = 0; k < 8; k++) {
            int lr = rg * 8 + k;
            int i = i0 + lr;
            int s0 = g_off_e[i], s1 = g_off_e[i + 1];
            float acc = 0.f;
            for (int p = s0; p < s1; p++) {
                int l = g_lst_e[p];
                int ld = lg_dst[l];
                bool win = true;
                for (int p2 = s0; p2 < s1; p2++) {
                    int l2 = g_lst_e[p2];
                    if (l2 > l && lg_dst[l2] == ld) win = false;
                }
                if (win) acc += g_ev[h*(EE*FE) + ld*FE + col];
            }
            acc *= g_nsa[h*NN + dst[i]];
            agg[lr][col] = acc;
        }
        __syncthreads();
        float a[8];
        float bb = ecb[col];
#pragma unroll
        for (int k = 0; k < 8; k++) a[k] = bb;
#pragma unroll 4
        for (int f = 0; f < FE; f++) {
            float w = g_ecWT[f*FEO + col];
#pragma unroll
            for (int k = 0; k < 8; k++) a[k] += agg[rg*8 + k][f] * w;
        }
#pragma unroll
        for (int k = 0; k < 8; k++) {
            int i = i0 + rg*8 + k;
            out[NODE_OUT_SZ + h*(EE*FEO) + i*FEO + col] = fmaxf(a[k], 0.f);
        }
    } else {
        // cleanup for next run
        int idx = (bid - 2048) * 128 + tid;       // 0..2047
        for (int i = idx; i < NN; i += 2048) { g_cnt_n[i] = 0; g_fc_n[i] = 0; }
        for (int i = idx; i < EE; i += 2048) { g_cnt_e[i] = 0; g_fc_e[i] = 0; }
        for (int i = idx; i < NH*4*FN; i += 2048) g_yn[i] = 0.f;
        for (int i = idx; i < NH*4*FE; i += 2048) g_ye[i] = 0.f;
        if (idx < NH*4) { g_ksn[idx] = 0.f; g_kse[idx] = 0.f; }
    }
}

// ---------------- launcher ----------------
extern "C" void kernel_launch(void* const* d_in, const int* in_sizes, int n_in,
                              void* d_out, int out_size)
{
    const float* node_inputs = (const float*)d_in[0];
    const float* edge_inputs = (const float*)d_in[1];
    const int*   src         = (const int*)d_in[2];
    const int*   dst         = (const int*)d_in[3];
    const int*   lg_src      = (const int*)d_in[4];
    const int*   lg_dst      = (const int*)d_in[5];
    const float* nqW = (const float*)d_in[6];
    const float* nqb = (const float*)d_in[7];
    const float* nkW = (const float*)d_in[8];
    const float* nkb = (const float*)d_in[9];
    const float* nvW = (const float*)d_in[10];
    const float* nvb = (const float*)d_in[11];
    const float* eqW = (const float*)d_in[12];
    const float* eqb = (const float*)d_in[13];
    const float* ekW = (const float*)d_in[14];
    const float* ekb = (const float*)d_in[15];
    const float* evW = (const float*)d_in[16];
    const float* evb = (const float*)d_in[17];
    const float* ncW = (const float*)d_in[18];
    const float* ncb = (const float*)d_in[19];
    const float* ecW = (const float*)d_in[20];
    const float* ecb = (const float*)d_in[21];
    float* out = (float*)d_out;

    prep_kernel<<<1120, 256>>>(node_inputs, edge_inputs, nkW, nkb, ekW, ekb,
                               src, lg_src, ncW, ecW, nqW, eqW);
    gemms_kernel<<<384, 256>>>(node_inputs, edge_inputs, nvW, nvb, evW, evb);
    scan_y_kernel<<<42, 1024>>>(node_inputs, edge_inputs);
    fill_t_kernel<<<176, 256>>>(src, lg_src, nqW, nqb, eqW, eqb);
    uc_kernel<<<388, 256>>>(nqb, eqb);
    scores_kernel<<<2560, 256>>>(node_inputs, edge_inputs);
    softmax_kernel<<<8, 1024>>>();
    out_kernel<<<2064, 128>>>(dst, lg_dst, ncb, ecb, out);
}